// round 9
// baseline (speedup 1.0000x reference)
#include <cuda_runtime.h>
#include <cstdint>

#define BB 256
#define TT 2048
#define II 128
#define HH 256
#define AA 8

typedef unsigned long long ull;

// 512MB scratch for xproj[b][t][h]
__device__ float g_xproj[(size_t)BB * TT * HH];

__device__ __forceinline__ ull ffma2(ull a, ull b, ull c) {
  ull d;
  asm("fma.rn.f32x2 %0, %1, %2, %3;" : "=l"(d) : "l"(a), "l"(b), "l"(c));
  return d;
}
__device__ __forceinline__ ull add2(ull a, ull b) {
  ull d;
  asm("add.rn.f32x2 %0, %1, %2;" : "=l"(d) : "l"(a), "l"(b));
  return d;
}
__device__ __forceinline__ ull pack2(float lo, float hi) {
  ull d;
  asm("mov.b64 %0, {%1, %2};" : "=l"(d) : "f"(lo), "f"(hi));
  return d;
}
__device__ __forceinline__ float hsum2(ull v) {
  float lo, hi;
  asm("mov.b64 {%0, %1}, %2;" : "=f"(lo), "=f"(hi) : "l"(v));
  return lo + hi;
}

// ---------------------------------------------------------------------------
// Kernel 1: xproj — proven R6 version (~1.13 ms).
// ---------------------------------------------------------------------------
__global__ void __launch_bounds__(512) xproj_kernel(
    const float* __restrict__ x, const float* __restrict__ W_ih) {
  __shared__ float sX[2][1024];
  __shared__ float sP[2][8 * 256];

  const int tid = threadIdx.x;
  const int j = tid & 255;
  const int kh = tid >> 8;

  ull w[32];
  {
    const float2* wp =
        reinterpret_cast<const float2*>(W_ih + j * II + kh * 64);
    #pragma unroll
    for (int i = 0; i < 32; ++i) {
      float2 v = __ldg(wp + i);
      w[i] = pack2(v.x, v.y);
    }
  }

  const size_t rowbase = (size_t)blockIdx.x * 256;
  const float4* xg4 = reinterpret_cast<const float4*>(x + rowbase * II);

  if (tid < 256) {
    reinterpret_cast<float4*>(sX[0])[tid] = __ldg(xg4 + tid);
  }
  __syncthreads();

  for (int c = 0; c < 32; ++c) {
    float4 pf;
    if (c < 31 && tid < 256) pf = __ldg(xg4 + (c + 1) * 256 + tid);

    const float* cur = sX[c & 1];
    ull acc[8];
    #pragma unroll
    for (int r = 0; r < 8; ++r) acc[r] = 0ull;

    #pragma unroll
    for (int r = 0; r < 8; ++r) {
      const ulonglong2* xr =
          reinterpret_cast<const ulonglong2*>(cur + r * II + kh * 64);
      #pragma unroll
      for (int q = 0; q < 16; ++q) {
        ulonglong2 xv = xr[q];
        acc[r] = ffma2(w[2 * q],     xv.x, acc[r]);
        acc[r] = ffma2(w[2 * q + 1], xv.y, acc[r]);
      }
    }

    float p[8];
    #pragma unroll
    for (int r = 0; r < 8; ++r) p[r] = hsum2(acc[r]);

    if (kh == 1) {
      #pragma unroll
      for (int r = 0; r < 8; ++r) sP[c & 1][r * 256 + j] = p[r];
    }
    if (c < 31 && tid < 256) {
      reinterpret_cast<float4*>(sX[(c + 1) & 1])[tid] = pf;
    }
    __syncthreads();
    if (kh == 0) {
      float* op = g_xproj + (rowbase + (size_t)c * 8) * HH + j;
      #pragma unroll
      for (int r = 0; r < 8; ++r) {
        op[r * HH] = p[r] + sP[c & 1][r * 256 + j];
      }
    }
  }
}

// ---------------------------------------------------------------------------
// Kernel 2: recurrence. 64 clusters x 2 CTAs x 512 threads; 4 batches per
// cluster. CTA rank r owns j in [128r, 128r+128) over ALL k — so W_hh slice
// (128x256 floats) lives ENTIRELY in registers (64 floats/thread), zero
// W smem traffic. h (4 batches x 256, padded 36/32-block) double-buffered
// in local smem; per step each CTA computes its j-half of h_new, stores it
// locally AND into the peer CTA's smem (st.shared::cluster), then
// barrier.cluster synchronizes + publishes. In-warp octet reduce via
// shfl_xor(1,2,4); every lane finalizes exactly one (j, b).
// ---------------------------------------------------------------------------
__global__ void __launch_bounds__(512, 1) __cluster_dims__(2, 1, 1)
recurrence_kernel(
    const float* __restrict__ hx, const float* __restrict__ W_hh,
    const float* __restrict__ W_actor, const float* __restrict__ W_critic,
    float* __restrict__ out) {
  // [2 parity][4 b][292]: per-b 8 k-blocks of 36 (32 data + 4 pad)
  __shared__ float shb[2 * 4 * 292];

  const int tid = threadIdx.x;
  uint32_t rank;
  asm("mov.u32 %0, %%cluster_ctarank;" : "=r"(rank));
  const uint32_t peer = rank ^ 1u;

  const int JL = tid >> 3;   // 0..63
  const int KH = tid & 7;    // 0..7
  const int j0g = (int)rank * 128 + 2 * JL;  // this thread's 2 global j's
  const int kb = KH * 32;
  const int b_base = (blockIdx.x >> 1) * 4;

  const int s0 = tid & 1;
  const int jf = j0g + s0;     // owned global j
  const int bf = KH >> 1;      // owned batch 0..3

  // ---- W entirely in registers: 2 j x 32 k = 32 ull ----
  ull w0[16], w1[16];
  {
    const float4* wp0 = reinterpret_cast<const float4*>(W_hh + j0g * HH + kb);
    const float4* wp1 =
        reinterpret_cast<const float4*>(W_hh + (j0g + 1) * HH + kb);
    #pragma unroll
    for (int i = 0; i < 8; ++i) {
      float4 f0 = __ldg(wp0 + i);
      float4 f1 = __ldg(wp1 + i);
      w0[2 * i]     = pack2(f0.x, f0.y);
      w0[2 * i + 1] = pack2(f0.z, f0.w);
      w1[2 * i]     = pack2(f1.x, f1.y);
      w1[2 * i + 1] = pack2(f1.z, f1.w);
    }
  }

  // ---- init h buffer 0 (full 4 batches, loaded locally from global) ----
  for (int idx = tid; idx < 4 * HH; idx += 512) {
    int b = idx >> 8, jj = idx & 255;
    shb[b * 292 + (jj >> 5) * 36 + (jj & 31)] = hx[(b_base + b) * HH + jj];
  }
  float h_old = hx[(b_base + bf) * HH + jf];
  __syncthreads();
  asm volatile("barrier.cluster.arrive.aligned;" ::: "memory");
  asm volatile("barrier.cluster.wait.aligned;" ::: "memory");

  const float* xqp = g_xproj + ((size_t)(b_base + bf) * TT) * HH + jf;
  float xq_cur = __ldg(xqp);

  uint32_t smem_base;
  asm("{ .reg .u64 t; cvta.to.shared.u64 t, %1; cvt.u32.u64 %0, t; }"
      : "=r"(smem_base) : "l"(shb));
  const int stoff = bf * 292 + (jf >> 5) * 36 + (jf & 31);

  for (int t = 0; t < TT; ++t) {
    const int rp = t & 1;
    float xq_nxt = 0.0f;
    if (t + 1 < TT) xq_nxt = __ldg(xqp + (size_t)(t + 1) * HH);

    const float* hb = shb + rp * 1168 + KH * 36;

    ull a0[4], a1[4];
    #pragma unroll
    for (int b = 0; b < 4; ++b) { a0[b] = 0ull; a1[b] = 0ull; }

    #pragma unroll
    for (int q = 0; q < 8; ++q) {
      #pragma unroll
      for (int b = 0; b < 4; ++b) {
        ulonglong2 v =
            *reinterpret_cast<const ulonglong2*>(hb + b * 292 + 4 * q);
        a0[b] = ffma2(w0[2 * q],     v.x, a0[b]);
        a1[b] = ffma2(w1[2 * q],     v.x, a1[b]);
        a0[b] = ffma2(w0[2 * q + 1], v.y, a0[b]);
        a1[b] = ffma2(w1[2 * q + 1], v.y, a1[b]);
      }
    }

    // ---- in-warp octet reduce-scatter over lane bits 0,1,2 ----
    const bool c0 = (tid & 1), c1 = (tid & 2), c2 = (tid & 4);
    ull k[4];
    #pragma unroll
    for (int b = 0; b < 4; ++b) {
      ull keep = c0 ? a1[b] : a0[b];
      ull give = c0 ? a0[b] : a1[b];
      k[b] = add2(keep, __shfl_xor_sync(0xffffffffu, give, 1));
    }
    ull m0, m1;
    {
      ull keep0 = c1 ? k[1] : k[0];
      ull give0 = c1 ? k[0] : k[1];
      m0 = add2(keep0, __shfl_xor_sync(0xffffffffu, give0, 2));
      ull keep1 = c1 ? k[3] : k[2];
      ull give1 = c1 ? k[2] : k[3];
      m1 = add2(keep1, __shfl_xor_sync(0xffffffffu, give1, 2));
    }
    ull keep = c2 ? m1 : m0;
    ull give = c2 ? m0 : m1;
    ull tot = add2(keep, __shfl_xor_sync(0xffffffffu, give, 4));

    // ---- finalize owned (bf, jf) ----
    float p = hsum2(tot) + xq_cur;
    h_old = 0.8f * h_old + 0.2f * fmaxf(p, 0.0f);
    const int widx = (rp ^ 1) * 1168 + stoff;
    shb[widx] = h_old;  // local copy
    {   // peer copy via DSMEM
      uint32_t laddr = smem_base + (uint32_t)widx * 4u;
      asm volatile(
          "{\n\t.reg .u32 ra;\n\t"
          "mapa.shared::cluster.u32 ra, %0, %1;\n\t"
          "st.shared::cluster.f32 [ra], %2;\n\t}"
          :: "r"(laddr), "r"(peer), "f"(h_old) : "memory");
    }
    xq_cur = xq_nxt;
    asm volatile("barrier.cluster.arrive.aligned;" ::: "memory");
    asm volatile("barrier.cluster.wait.aligned;" ::: "memory");
  }

  // -------- epilogue: final h in parity-0 buffer; rank outputs 2 batches ----
  const int bo0 = b_base + 2 * (int)rank;
  const int bo1 = bo0 + 1;
  const float* hf0 = shb + (2 * rank) * 292;
  const float* hf1 = shb + (2 * rank + 1) * 292;

  float* out_actor  = out;                 // [B][A]
  float* out_critic = out + BB * AA;       // [B]
  float* out_hx     = out + BB * AA + BB;  // [B][H]

  if (tid < HH) {
    int pj = (tid >> 5) * 36 + (tid & 31);
    out_hx[bo0 * HH + tid] = hf0[pj];
    out_hx[bo1 * HH + tid] = hf1[pj];
  }

  const int wid = tid >> 5, lane = tid & 31;
  if (wid < AA) {
    float pa0 = 0.f, pa1 = 0.f;
    for (int jj = lane; jj < HH; jj += 32) {
      int pj = (jj >> 5) * 36 + (jj & 31);
      float wa = W_actor[wid * HH + jj];
      pa0 += wa * hf0[pj];
      pa1 += wa * hf1[pj];
    }
    #pragma unroll
    for (int off = 16; off; off >>= 1) {
      pa0 += __shfl_down_sync(0xffffffffu, pa0, off);
      pa1 += __shfl_down_sync(0xffffffffu, pa1, off);
    }
    if (lane == 0) {
      out_actor[bo0 * AA + wid] = pa0;
      out_actor[bo1 * AA + wid] = pa1;
    }
  }
  if (wid == 8) {
    float pc0 = 0.f, pc1 = 0.f;
    for (int jj = lane; jj < HH; jj += 32) {
      int pj = (jj >> 5) * 36 + (jj & 31);
      float wc = W_critic[jj];
      pc0 += wc * hf0[pj];
      pc1 += wc * hf1[pj];
    }
    #pragma unroll
    for (int off = 16; off; off >>= 1) {
      pc0 += __shfl_down_sync(0xffffffffu, pc0, off);
      pc1 += __shfl_down_sync(0xffffffffu, pc1, off);
    }
    if (lane == 0) {
      out_critic[bo0] = pc0;
      out_critic[bo1] = pc1;
    }
  }
}

// ---------------------------------------------------------------------------
extern "C" void kernel_launch(void* const* d_in, const int* in_sizes, int n_in,
                              void* d_out, int out_size) {
  const float* x        = (const float*)d_in[0];
  const float* hx       = (const float*)d_in[1];
  const float* W_ih     = (const float*)d_in[2];
  const float* W_hh     = (const float*)d_in[3];
  const float* W_actor  = (const float*)d_in[4];
  const float* W_critic = (const float*)d_in[5];
  float* out = (float*)d_out;

  xproj_kernel<<<(BB * TT) / 256, 512>>>(x, W_ih);
  // 128 CTAs = 64 clusters of 2 (cluster dims baked into the kernel)
  recurrence_kernel<<<BB / 4 * 2, 512>>>(hx, W_hh, W_actor, W_critic, out);
}

// round 10
// speedup vs baseline: 1.2500x; 1.2500x over previous
#include <cuda_runtime.h>
#include <cstdint>

#define BB 256
#define TT 2048
#define II 128
#define HH 256
#define AA 8

typedef unsigned long long ull;

// 512MB scratch for xproj[b][t][h]
__device__ float g_xproj[(size_t)BB * TT * HH];

__device__ __forceinline__ ull ffma2(ull a, ull b, ull c) {
  ull d;
  asm("fma.rn.f32x2 %0, %1, %2, %3;" : "=l"(d) : "l"(a), "l"(b), "l"(c));
  return d;
}
__device__ __forceinline__ ull add2(ull a, ull b) {
  ull d;
  asm("add.rn.f32x2 %0, %1, %2;" : "=l"(d) : "l"(a), "l"(b));
  return d;
}
__device__ __forceinline__ ull pack2(float lo, float hi) {
  ull d;
  asm("mov.b64 %0, {%1, %2};" : "=l"(d) : "f"(lo), "f"(hi));
  return d;
}
__device__ __forceinline__ float hsum2(ull v) {
  float lo, hi;
  asm("mov.b64 {%0, %1}, %2;" : "=f"(lo), "=f"(hi) : "l"(v));
  return lo + hi;
}
__device__ __forceinline__ uint32_t smem_u32(const void* p) {
  uint32_t a;
  asm("{ .reg .u64 t; cvta.to.shared.u64 t, %1; cvt.u32.u64 %0, t; }"
      : "=r"(a) : "l"(p));
  return a;
}
__device__ __forceinline__ uint32_t mapa_u32(uint32_t addr, uint32_t rank) {
  uint32_t r;
  asm("mapa.shared::cluster.u32 %0, %1, %2;" : "=r"(r) : "r"(addr), "r"(rank));
  return r;
}
// async store to (possibly remote) cluster smem with tx signal on that CTA's bar
__device__ __forceinline__ void st_async_f32(uint32_t raddr, float v,
                                             uint32_t rbar) {
  asm volatile(
      "st.async.shared::cluster.mbarrier::complete_tx::bytes.f32 [%0], %1, [%2];"
      :: "r"(raddr), "f"(v), "r"(rbar) : "memory");
}
__device__ __forceinline__ void bar_wait_parity_cluster(uint32_t mbar,
                                                        uint32_t parity) {
  uint32_t done;
  asm volatile(
      "{\n\t.reg .pred p;\n\t"
      "mbarrier.try_wait.parity.acquire.cluster.shared::cta.b64 p, [%1], %2;\n\t"
      "selp.b32 %0, 1, 0, p;\n\t}"
      : "=r"(done) : "r"(mbar), "r"(parity) : "memory");
  while (!done) {
    asm volatile(
        "{\n\t.reg .pred p;\n\t"
        "mbarrier.try_wait.parity.acquire.cluster.shared::cta.b64 p, [%1], %2, 0x989680;\n\t"
        "selp.b32 %0, 1, 0, p;\n\t}"
        : "=r"(done) : "r"(mbar), "r"(parity) : "memory");
  }
}

// ---------------------------------------------------------------------------
// Kernel 1: xproj — proven R6 version (~1.13 ms).
// ---------------------------------------------------------------------------
__global__ void __launch_bounds__(512) xproj_kernel(
    const float* __restrict__ x, const float* __restrict__ W_ih) {
  __shared__ float sX[2][1024];
  __shared__ float sP[2][8 * 256];

  const int tid = threadIdx.x;
  const int j = tid & 255;
  const int kh = tid >> 8;

  ull w[32];
  {
    const float2* wp =
        reinterpret_cast<const float2*>(W_ih + j * II + kh * 64);
    #pragma unroll
    for (int i = 0; i < 32; ++i) {
      float2 v = __ldg(wp + i);
      w[i] = pack2(v.x, v.y);
    }
  }

  const size_t rowbase = (size_t)blockIdx.x * 256;
  const float4* xg4 = reinterpret_cast<const float4*>(x + rowbase * II);

  if (tid < 256) {
    reinterpret_cast<float4*>(sX[0])[tid] = __ldg(xg4 + tid);
  }
  __syncthreads();

  for (int c = 0; c < 32; ++c) {
    float4 pf;
    if (c < 31 && tid < 256) pf = __ldg(xg4 + (c + 1) * 256 + tid);

    const float* cur = sX[c & 1];
    ull acc[8];
    #pragma unroll
    for (int r = 0; r < 8; ++r) acc[r] = 0ull;

    #pragma unroll
    for (int r = 0; r < 8; ++r) {
      const ulonglong2* xr =
          reinterpret_cast<const ulonglong2*>(cur + r * II + kh * 64);
      #pragma unroll
      for (int q = 0; q < 16; ++q) {
        ulonglong2 xv = xr[q];
        acc[r] = ffma2(w[2 * q],     xv.x, acc[r]);
        acc[r] = ffma2(w[2 * q + 1], xv.y, acc[r]);
      }
    }

    float p[8];
    #pragma unroll
    for (int r = 0; r < 8; ++r) p[r] = hsum2(acc[r]);

    if (kh == 1) {
      #pragma unroll
      for (int r = 0; r < 8; ++r) sP[c & 1][r * 256 + j] = p[r];
    }
    if (c < 31 && tid < 256) {
      reinterpret_cast<float4*>(sX[(c + 1) & 1])[tid] = pf;
    }
    __syncthreads();
    if (kh == 0) {
      float* op = g_xproj + (rowbase + (size_t)c * 8) * HH + j;
      #pragma unroll
      for (int r = 0; r < 8; ++r) {
        op[r * HH] = p[r] + sP[c & 1][r * 256 + j];
      }
    }
  }
}

// ---------------------------------------------------------------------------
// Kernel 2: recurrence. 64 clusters x 2 CTAs x 512 threads; 4 batches per
// cluster. CTA rank r owns j in [128r, 128r+128) over ALL k: its W slice
// (128x256) lives ENTIRELY in registers (64 floats/thread). Full h (4 b) is
// double-buffered in each CTA's smem. Per step: broadcast h LDS + FFMA2;
// in-warp octet reduce-scatter (shfl_xor 1,2,4) -> each lane owns one (j,b);
// owner writes h_new to BOTH CTAs' buffers via st.async + mbarrier tx
// (4096B expected = 512 self + 512 peer floats). Two alternating mbars.
// No __syncthreads, no barrier.cluster (no L1 flush) in the loop.
// ---------------------------------------------------------------------------
__global__ void __launch_bounds__(512, 1) __cluster_dims__(2, 1, 1)
recurrence_kernel(
    const float* __restrict__ hx, const float* __restrict__ W_hh,
    const float* __restrict__ W_actor, const float* __restrict__ W_critic,
    float* __restrict__ out) {
  // [2 parity][4 b][288 = 8 blocks x 36]
  __shared__ float shb[2 * 4 * 288];
  __shared__ ull bars[2];

  const int tid = threadIdx.x;
  uint32_t rank;
  asm("mov.u32 %0, %%cluster_ctarank;" : "=r"(rank));
  const uint32_t peerr = rank ^ 1u;

  const int JL = tid >> 3;   // 0..63
  const int KH = tid & 7;    // 0..7
  const int j0g = (int)rank * 128 + 2 * JL;
  const int kb = KH * 32;
  const int b_base = (blockIdx.x >> 1) * 4;

  const int jf = j0g + (tid & 1);  // owned global j
  const int bf = KH >> 1;          // owned batch 0..3

  // ---- W entirely in registers: 2 j x 32 k = 32 ull ----
  ull w0[16], w1[16];
  {
    const float4* wp0 = reinterpret_cast<const float4*>(W_hh + j0g * HH + kb);
    const float4* wp1 =
        reinterpret_cast<const float4*>(W_hh + (j0g + 1) * HH + kb);
    #pragma unroll
    for (int i = 0; i < 8; ++i) {
      float4 f0 = __ldg(wp0 + i);
      float4 f1 = __ldg(wp1 + i);
      w0[2 * i]     = pack2(f0.x, f0.y);
      w0[2 * i + 1] = pack2(f0.z, f0.w);
      w1[2 * i]     = pack2(f1.x, f1.y);
      w1[2 * i + 1] = pack2(f1.z, f1.w);
    }
  }

  // ---- init h buffer 0 (all 4 batches) + mbars ----
  for (int idx = tid; idx < 4 * HH; idx += 512) {
    int b = idx >> 8, jj = idx & 255;
    shb[b * 288 + (jj >> 5) * 36 + (jj & 31)] = hx[(b_base + b) * HH + jj];
  }
  float h_old = hx[(b_base + bf) * HH + jf];
  const uint32_t bars_u32 = smem_u32(bars);
  if (tid == 0) {
    asm volatile("mbarrier.init.shared.b64 [%0], 1;" :: "r"(bars_u32)
                 : "memory");
    asm volatile("mbarrier.init.shared.b64 [%0], 1;" :: "r"(bars_u32 + 8)
                 : "memory");
  }
  __syncthreads();
  asm volatile("barrier.cluster.arrive.aligned;" ::: "memory");
  asm volatile("barrier.cluster.wait.aligned;" ::: "memory");

  // cluster-aperture addresses (computed once; aperture is linear per rank)
  const uint32_t shb_u32   = smem_u32(shb);
  const uint32_t self_shb  = mapa_u32(shb_u32, rank);
  const uint32_t peer_shb  = mapa_u32(shb_u32, peerr);
  const uint32_t self_bar0 = mapa_u32(bars_u32, rank);
  const uint32_t peer_bar0 = mapa_u32(bars_u32, peerr);

  const float* xqp = g_xproj + ((size_t)(b_base + bf) * TT) * HH + jf;
  float xq_cur = __ldg(xqp);

  const float* hk = shb + KH * 36;               // k-block base (parity 0)
  const uint32_t woff_base =
      (uint32_t)(bf * 288 + (jf >> 5) * 36 + (jf & 31)) * 4u;

  for (int t = 0; t < TT; ++t) {
    const int rp = t & 1;
    float xq_nxt = 0.0f;
    if (t + 1 < TT) xq_nxt = __ldg(xqp + (size_t)(t + 1) * HH);

    const float* hb = hk + rp * 1152;

    ull a0[4], a1[4];
    #pragma unroll
    for (int b = 0; b < 4; ++b) { a0[b] = 0ull; a1[b] = 0ull; }

    #pragma unroll
    for (int q = 0; q < 8; ++q) {
      #pragma unroll
      for (int b = 0; b < 4; ++b) {
        ulonglong2 v =
            *reinterpret_cast<const ulonglong2*>(hb + b * 288 + 4 * q);
        a0[b] = ffma2(w0[2 * q],     v.x, a0[b]);
        a1[b] = ffma2(w1[2 * q],     v.x, a1[b]);
        a0[b] = ffma2(w0[2 * q + 1], v.y, a0[b]);
        a1[b] = ffma2(w1[2 * q + 1], v.y, a1[b]);
      }
    }

    // ---- in-warp octet reduce-scatter over lane bits 0,1,2 ----
    const bool c0 = (tid & 1), c1 = (tid & 2), c2 = (tid & 4);
    ull k[4];
    #pragma unroll
    for (int b = 0; b < 4; ++b) {
      ull keep = c0 ? a1[b] : a0[b];
      ull give = c0 ? a0[b] : a1[b];
      k[b] = add2(keep, __shfl_xor_sync(0xffffffffu, give, 1));
    }
    ull m0, m1;
    {
      ull keep0 = c1 ? k[1] : k[0];
      ull give0 = c1 ? k[0] : k[1];
      m0 = add2(keep0, __shfl_xor_sync(0xffffffffu, give0, 2));
      ull keep1 = c1 ? k[3] : k[2];
      ull give1 = c1 ? k[2] : k[3];
      m1 = add2(keep1, __shfl_xor_sync(0xffffffffu, give1, 2));
    }
    ull keep = c2 ? m1 : m0;
    ull give = c2 ? m0 : m1;
    ull tot = add2(keep, __shfl_xor_sync(0xffffffffu, give, 4));

    // ---- finalize owned (bf, jf); publish to BOTH CTAs via st.async ----
    float p = hsum2(tot) + xq_cur;
    h_old = 0.8f * h_old + 0.2f * fmaxf(p, 0.0f);
    const uint32_t woff = (uint32_t)((rp ^ 1) * 1152 * 4) + woff_base;
    const uint32_t baroff = (uint32_t)((t & 1) * 8);
    st_async_f32(self_shb + woff, h_old, self_bar0 + baroff);
    st_async_f32(peer_shb + woff, h_old, peer_bar0 + baroff);
    if (tid == 0) {
      asm volatile("mbarrier.arrive.expect_tx.shared.b64 _, [%0], 4096;"
                   :: "r"(bars_u32 + baroff) : "memory");
    }
    xq_cur = xq_nxt;
    bar_wait_parity_cluster(bars_u32 + baroff, (uint32_t)((t >> 1) & 1));
  }

  // -------- epilogue: final h in parity-0 buffer; rank outputs 2 batches ----
  const int bo0 = b_base + 2 * (int)rank;
  const int bo1 = bo0 + 1;
  const float* hf0 = shb + (2 * rank) * 288;
  const float* hf1 = shb + (2 * rank + 1) * 288;

  float* out_actor  = out;                 // [B][A]
  float* out_critic = out + BB * AA;       // [B]
  float* out_hx     = out + BB * AA + BB;  // [B][H]

  if (tid < HH) {
    int pj = (tid >> 5) * 36 + (tid & 31);
    out_hx[bo0 * HH + tid] = hf0[pj];
    out_hx[bo1 * HH + tid] = hf1[pj];
  }

  const int wid = tid >> 5, lane = tid & 31;
  if (wid < AA) {
    float pa0 = 0.f, pa1 = 0.f;
    for (int jj = lane; jj < HH; jj += 32) {
      int pj = (jj >> 5) * 36 + (jj & 31);
      float wa = W_actor[wid * HH + jj];
      pa0 += wa * hf0[pj];
      pa1 += wa * hf1[pj];
    }
    #pragma unroll
    for (int off = 16; off; off >>= 1) {
      pa0 += __shfl_down_sync(0xffffffffu, pa0, off);
      pa1 += __shfl_down_sync(0xffffffffu, pa1, off);
    }
    if (lane == 0) {
      out_actor[bo0 * AA + wid] = pa0;
      out_actor[bo1 * AA + wid] = pa1;
    }
  }
  if (wid == 8) {
    float pc0 = 0.f, pc1 = 0.f;
    for (int jj = lane; jj < HH; jj += 32) {
      int pj = (jj >> 5) * 36 + (jj & 31);
      float wc = W_critic[jj];
      pc0 += wc * hf0[pj];
      pc1 += wc * hf1[pj];
    }
    #pragma unroll
    for (int off = 16; off; off >>= 1) {
      pc0 += __shfl_down_sync(0xffffffffu, pc0, off);
      pc1 += __shfl_down_sync(0xffffffffu, pc1, off);
    }
    if (lane == 0) {
      out_critic[bo0] = pc0;
      out_critic[bo1] = pc1;
    }
  }
  // keep cluster alive until both CTAs are done reading peer-written smem
  asm volatile("barrier.cluster.arrive.aligned;" ::: "memory");
  asm volatile("barrier.cluster.wait.aligned;" ::: "memory");
}

// ---------------------------------------------------------------------------
extern "C" void kernel_launch(void* const* d_in, const int* in_sizes, int n_in,
                              void* d_out, int out_size) {
  const float* x        = (const float*)d_in[0];
  const float* hx       = (const float*)d_in[1];
  const float* W_ih     = (const float*)d_in[2];
  const float* W_hh     = (const float*)d_in[3];
  const float* W_actor  = (const float*)d_in[4];
  const float* W_critic = (const float*)d_in[5];
  float* out = (float*)d_out;

  xproj_kernel<<<(BB * TT) / 256, 512>>>(x, W_ih);
  // 128 CTAs = 64 clusters of 2 (cluster dims baked into the kernel)
  recurrence_kernel<<<128, 512>>>(hx, W_hh, W_actor, W_critic, out);
}

// round 11
// speedup vs baseline: 1.3330x; 1.0664x over previous
#include <cuda_runtime.h>
#include <cstdint>

#define BB 256
#define TT 2048
#define II 128
#define HH 256
#define AA 8

typedef unsigned long long ull;

// 512MB scratch for xproj[b][t][h]
__device__ float g_xproj[(size_t)BB * TT * HH];

__device__ __forceinline__ ull ffma2(ull a, ull b, ull c) {
  ull d;
  asm("fma.rn.f32x2 %0, %1, %2, %3;" : "=l"(d) : "l"(a), "l"(b), "l"(c));
  return d;
}
__device__ __forceinline__ ull add2(ull a, ull b) {
  ull d;
  asm("add.rn.f32x2 %0, %1, %2;" : "=l"(d) : "l"(a), "l"(b));
  return d;
}
__device__ __forceinline__ ull pack2(float lo, float hi) {
  ull d;
  asm("mov.b64 %0, {%1, %2};" : "=l"(d) : "f"(lo), "f"(hi));
  return d;
}
__device__ __forceinline__ float hsum2(ull v) {
  float lo, hi;
  asm("mov.b64 {%0, %1}, %2;" : "=f"(lo), "=f"(hi) : "l"(v));
  return lo + hi;
}
__device__ __forceinline__ uint32_t smem_u32(const void* p) {
  uint32_t a;
  asm("{ .reg .u64 t; cvta.to.shared.u64 t, %1; cvt.u32.u64 %0, t; }"
      : "=r"(a) : "l"(p));
  return a;
}
__device__ __forceinline__ uint32_t mapa_u32(uint32_t addr, uint32_t rank) {
  uint32_t r;
  asm("mapa.shared::cluster.u32 %0, %1, %2;" : "=r"(r) : "r"(addr), "r"(rank));
  return r;
}
__device__ __forceinline__ void st_async_b64(uint32_t raddr, ull v,
                                             uint32_t rbar) {
  asm volatile(
      "st.async.shared::cluster.mbarrier::complete_tx::bytes.b64 [%0], %1, [%2];"
      :: "r"(raddr), "l"(v), "r"(rbar) : "memory");
}
__device__ __forceinline__ void st_async_f32(uint32_t raddr, float v,
                                             uint32_t rbar) {
  asm volatile(
      "st.async.shared::cluster.mbarrier::complete_tx::bytes.f32 [%0], %1, [%2];"
      :: "r"(raddr), "f"(v), "r"(rbar) : "memory");
}
__device__ __forceinline__ void bar_wait_parity_cluster(uint32_t mbar,
                                                        uint32_t parity) {
  uint32_t done;
  asm volatile(
      "{\n\t.reg .pred p;\n\t"
      "mbarrier.try_wait.parity.acquire.cluster.shared::cta.b64 p, [%1], %2;\n\t"
      "selp.b32 %0, 1, 0, p;\n\t}"
      : "=r"(done) : "r"(mbar), "r"(parity) : "memory");
  while (!done) {
    asm volatile(
        "{\n\t.reg .pred p;\n\t"
        "mbarrier.try_wait.parity.acquire.cluster.shared::cta.b64 p, [%1], %2, 0x989680;\n\t"
        "selp.b32 %0, 1, 0, p;\n\t}"
        : "=r"(done) : "r"(mbar), "r"(parity) : "memory");
  }
}

// ---------------------------------------------------------------------------
// Kernel 1: xproj — proven R6 version (~1.13 ms).
// ---------------------------------------------------------------------------
__global__ void __launch_bounds__(512) xproj_kernel(
    const float* __restrict__ x, const float* __restrict__ W_ih) {
  __shared__ float sX[2][1024];
  __shared__ float sP[2][8 * 256];

  const int tid = threadIdx.x;
  const int j = tid & 255;
  const int kh = tid >> 8;

  ull w[32];
  {
    const float2* wp =
        reinterpret_cast<const float2*>(W_ih + j * II + kh * 64);
    #pragma unroll
    for (int i = 0; i < 32; ++i) {
      float2 v = __ldg(wp + i);
      w[i] = pack2(v.x, v.y);
    }
  }

  const size_t rowbase = (size_t)blockIdx.x * 256;
  const float4* xg4 = reinterpret_cast<const float4*>(x + rowbase * II);

  if (tid < 256) {
    reinterpret_cast<float4*>(sX[0])[tid] = __ldg(xg4 + tid);
  }
  __syncthreads();

  for (int c = 0; c < 32; ++c) {
    float4 pf;
    if (c < 31 && tid < 256) pf = __ldg(xg4 + (c + 1) * 256 + tid);

    const float* cur = sX[c & 1];
    ull acc[8];
    #pragma unroll
    for (int r = 0; r < 8; ++r) acc[r] = 0ull;

    #pragma unroll
    for (int r = 0; r < 8; ++r) {
      const ulonglong2* xr =
          reinterpret_cast<const ulonglong2*>(cur + r * II + kh * 64);
      #pragma unroll
      for (int q = 0; q < 16; ++q) {
        ulonglong2 xv = xr[q];
        acc[r] = ffma2(w[2 * q],     xv.x, acc[r]);
        acc[r] = ffma2(w[2 * q + 1], xv.y, acc[r]);
      }
    }

    float p[8];
    #pragma unroll
    for (int r = 0; r < 8; ++r) p[r] = hsum2(acc[r]);

    if (kh == 1) {
      #pragma unroll
      for (int r = 0; r < 8; ++r) sP[c & 1][r * 256 + j] = p[r];
    }
    if (c < 31 && tid < 256) {
      reinterpret_cast<float4*>(sX[(c + 1) & 1])[tid] = pf;
    }
    __syncthreads();
    if (kh == 0) {
      float* op = g_xproj + (rowbase + (size_t)c * 8) * HH + j;
      #pragma unroll
      for (int r = 0; r < 8; ++r) {
        op[r * HH] = p[r] + sP[c & 1][r * 256 + j];
      }
    }
  }
}

// ---------------------------------------------------------------------------
// Kernel 2: recurrence. 64 clusters x 2 CTAs x 512 threads; 4 batches per
// cluster. K-SPLIT across the cluster: CTA rank r owns k in [128r, 128r+128)
// for ALL 256 j and 4 batches -> W slice = 64 floats/thread, ENTIRELY in
// registers. Key property: a CTA only ever READS h-components in its own
// k-range, which are exactly the ones it FINALIZES -> no h exchange; only
// j-partials for the peer's range cross (2048B/step as 256 b64 st.async).
// Thread (jg = tid>>2 -> j in {2jg,2jg+1}; kq = tid&3 -> 32-k window).
// In-quad shfl reduce (xor 1, xor 2) -> each lane owns (j, b-pair) packed
// f32x2. Finalize: 512 threads x 1 item. 2 syncthreads + 1 mbar wait/step.
// ---------------------------------------------------------------------------
__global__ void __launch_bounds__(512, 1) __cluster_dims__(2, 1, 1)
recurrence_kernel(
    const float* __restrict__ hx, const float* __restrict__ W_hh,
    const float* __restrict__ W_actor, const float* __restrict__ W_critic,
    float* __restrict__ out) {
  // h: [2 parity][4 b][4 kblk][36 pad]  (148 floats per b, 592 per parity)
  __shared__ __align__(16) float shh[2 * 592];
  __shared__ __align__(16) ull part_loc[256];       // [jl][bp]
  __shared__ __align__(16) ull part_rem[2][256];    // peer-written, by t&1
  __shared__ __align__(16) float hfull[4 * 260];    // epilogue full h
  __shared__ ull bars[2];

  const int tid = threadIdx.x;
  uint32_t rank;
  asm("mov.u32 %0, %%cluster_ctarank;" : "=r"(rank));
  const uint32_t peerr = rank ^ 1u;

  const int jg = tid >> 2;        // 0..127 -> j pair {2jg, 2jg+1}
  const int kq = tid & 3;         // 32-k window within CTA's 128-k half
  const int b_base = (blockIdx.x >> 1) * 4;

  // ---- W fully in registers: 2 j x 32 k = 32 ull ----
  ull w0[16], w1[16];
  {
    const int kg = (int)rank * 128 + kq * 32;
    const float4* wp0 =
        reinterpret_cast<const float4*>(W_hh + (2 * jg) * HH + kg);
    const float4* wp1 =
        reinterpret_cast<const float4*>(W_hh + (2 * jg + 1) * HH + kg);
    #pragma unroll
    for (int q = 0; q < 8; ++q) {
      float4 f0 = __ldg(wp0 + q);
      float4 f1 = __ldg(wp1 + q);
      w0[2 * q]     = pack2(f0.x, f0.y);
      w0[2 * q + 1] = pack2(f0.z, f0.w);
      w1[2 * q]     = pack2(f1.x, f1.y);
      w1[2 * q + 1] = pack2(f1.z, f1.w);
    }
  }

  // ---- finalize mapping: thread -> (fjl, fb); init h(0) ----
  const int fjl = tid >> 2;       // local k/j index 0..127
  const int fb  = tid & 3;        // batch within cluster
  const int fjg = (int)rank * 128 + fjl;  // global j
  float h_old = hx[(b_base + fb) * HH + fjg];
  shh[fb * 148 + (fjl >> 5) * 36 + (fjl & 31)] = h_old;

  const uint32_t bars_u32 = smem_u32(bars);
  if (tid == 0) {
    asm volatile("mbarrier.init.shared.b64 [%0], 1;" :: "r"(bars_u32)
                 : "memory");
    asm volatile("mbarrier.init.shared.b64 [%0], 1;" :: "r"(bars_u32 + 8)
                 : "memory");
  }
  __syncthreads();
  asm volatile("barrier.cluster.arrive.aligned;" ::: "memory");
  asm volatile("barrier.cluster.wait.aligned;" ::: "memory");

  const uint32_t peer_part = mapa_u32(smem_u32(part_rem), peerr);
  const uint32_t peer_bars = mapa_u32(bars_u32, peerr);
  const uint32_t peer_hfull = mapa_u32(smem_u32(hfull), peerr);

  const float* xqp = g_xproj + ((size_t)(b_base + fb) * TT) * HH + fjg;
  float xq_cur = __ldg(xqp);

  const int sidx = tid & 1;       // j parity owned after reduce
  const int bp = (tid >> 1) & 1;  // batch pair owned after reduce
  const int jown = 2 * jg + sidx;
  const int pidx = (jown & 127) * 2 + bp;      // partial slot (ull)
  const bool own_range = ((jown >> 7) == (int)rank);

  for (int t = 0; t < TT; ++t) {
    const int rp = t & 1;
    float xq_nxt = 0.0f;
    if (t + 1 < TT) xq_nxt = __ldg(xqp + (size_t)(t + 1) * HH);

    // ---- fma phase: partials over own k-window for all j, 4 batches ----
    const float* hb = shh + rp * 592 + kq * 36;
    ull a0[4], a1[4];
    #pragma unroll
    for (int b = 0; b < 4; ++b) { a0[b] = 0ull; a1[b] = 0ull; }

    #pragma unroll
    for (int q = 0; q < 8; ++q) {
      #pragma unroll
      for (int b = 0; b < 4; ++b) {
        ulonglong2 v =
            *reinterpret_cast<const ulonglong2*>(hb + b * 148 + 4 * q);
        a0[b] = ffma2(w0[2 * q],     v.x, a0[b]);
        a1[b] = ffma2(w1[2 * q],     v.x, a1[b]);
        a0[b] = ffma2(w0[2 * q + 1], v.y, a0[b]);
        a1[b] = ffma2(w1[2 * q + 1], v.y, a1[b]);
      }
    }

    // ---- in-quad reduce-scatter (lane bits 0,1 = kq bits) ----
    const bool c0 = (tid & 1), c1 = (tid & 2);
    ull k1[4];
    #pragma unroll
    for (int b = 0; b < 4; ++b) {
      ull keep = c0 ? a1[b] : a0[b];
      ull give = c0 ? a0[b] : a1[b];
      k1[b] = add2(keep, __shfl_xor_sync(0xffffffffu, give, 1));
    }
    ull m0, m1;
    {
      ull keep = c1 ? k1[2] : k1[0];
      ull give = c1 ? k1[0] : k1[2];
      m0 = add2(keep, __shfl_xor_sync(0xffffffffu, give, 2));
    }
    {
      ull keep = c1 ? k1[3] : k1[1];
      ull give = c1 ? k1[1] : k1[3];
      m1 = add2(keep, __shfl_xor_sync(0xffffffffu, give, 2));
    }
    // lane owns partial of (j = jown) for batches (2bp, 2bp+1)
    ull pk = pack2(hsum2(m0), hsum2(m1));

    if (own_range) {
      part_loc[pidx] = pk;
    } else {
      st_async_b64(peer_part + (uint32_t)((rp * 256 + pidx) * 8), pk,
                   peer_bars + (uint32_t)(rp * 8));
    }
    if (tid == 0) {
      asm volatile("mbarrier.arrive.expect_tx.shared.b64 _, [%0], 2048;"
                   :: "r"(bars_u32 + (uint32_t)(rp * 8)) : "memory");
    }
    __syncthreads();  // local partials visible
    bar_wait_parity_cluster(bars_u32 + (uint32_t)(rp * 8),
                            (uint32_t)((t >> 1) & 1));

    // ---- finalize own (fjl, fb): local + peer partial + xq ----
    {
      const float* lpp = reinterpret_cast<const float*>(part_loc);
      const float* rpp = reinterpret_cast<const float*>(part_rem[rp]);
      const int foff = fjl * 4 + (fb >> 1) * 2 + (fb & 1);
      float p = lpp[foff] + rpp[foff] + xq_cur;
      h_old = 0.8f * h_old + 0.2f * fmaxf(p, 0.0f);
      shh[(rp ^ 1) * 592 + fb * 148 + (fjl >> 5) * 36 + (fjl & 31)] = h_old;
    }
    xq_cur = xq_nxt;
    __syncthreads();  // h_new visible before next fma; protects part_loc WAR
  }

  // -------- epilogue --------
  float* out_actor  = out;                 // [B][A]
  float* out_critic = out + BB * AA;       // [B]
  float* out_hx     = out + BB * AA + BB;  // [B][H]

  // each thread owns final h of (fb, fjg)
  out_hx[(b_base + fb) * HH + fjg] = h_old;

  // exchange h halves -> both CTAs get full h (bars[0], next parity = 0)
  hfull[fb * 260 + fjg] = h_old;
  st_async_f32(peer_hfull + (uint32_t)((fb * 260 + fjg) * 4), h_old,
               peer_bars);
  if (tid == 0) {
    asm volatile("mbarrier.arrive.expect_tx.shared.b64 _, [%0], 2048;"
                 :: "r"(bars_u32) : "memory");
  }
  __syncthreads();
  bar_wait_parity_cluster(bars_u32, 0u);

  // actor/critic for this rank's 2 batches
  const int bo0 = b_base + 2 * (int)rank;
  const int bo1 = bo0 + 1;
  const float* hf0 = hfull + (2 * rank) * 260;
  const float* hf1 = hfull + (2 * rank + 1) * 260;

  const int wid = tid >> 5, lane = tid & 31;
  if (wid < AA) {
    float pa0 = 0.f, pa1 = 0.f;
    for (int jj = lane; jj < HH; jj += 32) {
      float wa = W_actor[wid * HH + jj];
      pa0 += wa * hf0[jj];
      pa1 += wa * hf1[jj];
    }
    #pragma unroll
    for (int off = 16; off; off >>= 1) {
      pa0 += __shfl_down_sync(0xffffffffu, pa0, off);
      pa1 += __shfl_down_sync(0xffffffffu, pa1, off);
    }
    if (lane == 0) {
      out_actor[bo0 * AA + wid] = pa0;
      out_actor[bo1 * AA + wid] = pa1;
    }
  }
  if (wid == 8) {
    float pc0 = 0.f, pc1 = 0.f;
    for (int jj = lane; jj < HH; jj += 32) {
      float wc = W_critic[jj];
      pc0 += wc * hf0[jj];
      pc1 += wc * hf1[jj];
    }
    #pragma unroll
    for (int off = 16; off; off >>= 1) {
      pc0 += __shfl_down_sync(0xffffffffu, pc0, off);
      pc1 += __shfl_down_sync(0xffffffffu, pc1, off);
    }
    if (lane == 0) {
      out_critic[bo0] = pc0;
      out_critic[bo1] = pc1;
    }
  }
  asm volatile("barrier.cluster.arrive.aligned;" ::: "memory");
  asm volatile("barrier.cluster.wait.aligned;" ::: "memory");
}

// ---------------------------------------------------------------------------
extern "C" void kernel_launch(void* const* d_in, const int* in_sizes, int n_in,
                              void* d_out, int out_size) {
  const float* x        = (const float*)d_in[0];
  const float* hx       = (const float*)d_in[1];
  const float* W_ih     = (const float*)d_in[2];
  const float* W_hh     = (const float*)d_in[3];
  const float* W_actor  = (const float*)d_in[4];
  const float* W_critic = (const float*)d_in[5];
  float* out = (float*)d_out;

  xproj_kernel<<<(BB * TT) / 256, 512>>>(x, W_ih);
  // 128 CTAs = 64 clusters of 2; 4 batches per cluster
  recurrence_kernel<<<128, 512>>>(hx, W_hh, W_actor, W_critic, out);
}